// round 1
// baseline (speedup 1.0000x reference)
#include <cuda_runtime.h>
#include <math.h>

#define BB 2
#define TT 2048
#define CC 1024
#define HH 16
#define DD 64
#define NR 65                      // 2*MAXREL+1
#define BH (BB*HH)                 // 32
#define BT (BB*TT)                 // 4096

// ---------------- device scratch (no allocations allowed) ----------------
__device__ float g_q[BH*TT*DD];        // 16 MB   [bh][t][d]
__device__ float g_k[BH*TT*DD];        // 16 MB
__device__ float g_v[BH*TT*DD];        // 16 MB
__device__ float g_qrel[BH*TT*NR];     // 17 MB   [bh][t][r]
__device__ float g_o[BT*CC];           // 16 MB   [b*T+t][h*64+d]  (pre-proj context)
__device__ float g_y[BT*CC];           // fallback y sink
__device__ float g_att[(size_t)BH*TT*TT]; // 537 MB fallback att sink

// ---------------- small float4 helpers ----------------
__device__ __forceinline__ float dot4(float4 a, float4 b) {
    return a.x*b.x + a.y*b.y + a.z*b.z + a.w*b.w;
}

// =====================================================================
// SGEMM: C = A[4096,1024] @ B[1024,N] + bias
// MODE 0: A = x param, scatter output into g_q/g_k/g_v head-major (N=3072)
// MODE 1: A = g_o, plain row-major output to Cout (or g_y if null) (N=1024)
// 128x128 tile, BK=16, 256 threads, 8x8 register micro-tile.
// =====================================================================
template<int MODE>
__global__ __launch_bounds__(256) void sgemm_kernel(
    const float* __restrict__ Ain, const float* __restrict__ Bm,
    const float* __restrict__ bias, float* __restrict__ Cout, int N)
{
    const int K = 1024;
    __shared__ float As[16][132];
    __shared__ float Bs[16][132];

    const float* A = (MODE == 0) ? Ain : (const float*)g_o;

    const int tid  = threadIdx.x;
    const int row0 = blockIdx.y * 128;
    const int col0 = blockIdx.x * 128;
    const int tr   = tid >> 4;   // 0..15
    const int tc   = tid & 15;   // 0..15

    float acc[8][8];
    #pragma unroll
    for (int i = 0; i < 8; i++)
        #pragma unroll
        for (int j = 0; j < 8; j++) acc[i][j] = 0.f;

    for (int k0 = 0; k0 < K; k0 += 16) {
        // load A tile 128x16 (transposed into As[k][m])
        #pragma unroll
        for (int lv = 0; lv < 2; lv++) {
            int li = tid + 256*lv;
            int ar = li >> 2, ac4 = li & 3;
            float4 v = *(const float4*)&A[(size_t)(row0 + ar)*K + k0 + ac4*4];
            As[ac4*4+0][ar] = v.x;
            As[ac4*4+1][ar] = v.y;
            As[ac4*4+2][ar] = v.z;
            As[ac4*4+3][ar] = v.w;
        }
        // load B tile 16x128
        #pragma unroll
        for (int lv = 0; lv < 2; lv++) {
            int li = tid + 256*lv;
            int br = li >> 5, bc4 = li & 31;
            *(float4*)&Bs[br][bc4*4] =
                *(const float4*)&Bm[(size_t)(k0 + br)*N + col0 + bc4*4];
        }
        __syncthreads();

        #pragma unroll
        for (int kk = 0; kk < 16; kk++) {
            float a[8], b[8];
            *(float4*)&a[0] = *(float4*)&As[kk][tr*8];
            *(float4*)&a[4] = *(float4*)&As[kk][tr*8+4];
            *(float4*)&b[0] = *(float4*)&Bs[kk][tc*8];
            *(float4*)&b[4] = *(float4*)&Bs[kk][tc*8+4];
            #pragma unroll
            for (int i = 0; i < 8; i++)
                #pragma unroll
                for (int j = 0; j < 8; j++)
                    acc[i][j] += a[i]*b[j];
        }
        __syncthreads();
    }

    #pragma unroll
    for (int i = 0; i < 8; i++) {
        int r = row0 + tr*8 + i;
        #pragma unroll
        for (int j = 0; j < 8; j++) {
            int c = col0 + tc*8 + j;
            float v = acc[i][j] + bias[c];
            if (MODE == 0) {
                int which = c >> 10;           // 0=q 1=k 2=v
                int hh    = (c >> 6) & 15;
                int dd    = c & 63;
                int b_    = r >> 11;
                int t_    = r & 2047;
                size_t di = ((size_t)(b_*HH + hh)*TT + t_)*DD + dd;
                float* dst = (which == 0) ? g_q : (which == 1) ? g_k : g_v;
                dst[di] = v;
            } else {
                float* dst = Cout ? Cout : g_y;
                dst[(size_t)r*N + c] = v;
            }
        }
    }
}

// =====================================================================
// qrel[bh*T + t][r] = q[bh][t][:] . rel_k_table[r][:]
// block handles 32 rows; rel table + q rows cached in smem.
// =====================================================================
__global__ __launch_bounds__(256) void qrel_kernel(const float* __restrict__ rel)
{
    __shared__ float rs[NR*64];   // 4160
    __shared__ float qs[32*64];   // 2048
    const int tid = threadIdx.x;
    const int r0  = blockIdx.x * 32;

    for (int i = tid; i < NR*16; i += 256)
        ((float4*)rs)[i] = ((const float4*)rel)[i];
    for (int i = tid; i < 32*16; i += 256) {
        int t = i >> 4, d4 = i & 15;
        *(float4*)&qs[t*64 + d4*4] = *(const float4*)&g_q[(size_t)(r0+t)*64 + d4*4];
    }
    __syncthreads();

    for (int i = tid; i < 32*NR; i += 256) {
        int t = i / NR, r = i % NR;
        const float4* qq = (const float4*)&qs[t*64];
        const float4* rr = (const float4*)&rs[r*64];
        float acc = 0.f;
        #pragma unroll
        for (int d4 = 0; d4 < 16; d4++) acc += dot4(qq[d4], rr[d4]);
        g_qrel[(size_t)(r0+t)*NR + r] = acc;
    }
}

// =====================================================================
// Attention: block = (qt, bh), 16 q-rows. Full S row-block in smem.
//   1. S = Q K^T + qrel-gather, scaled (causal: only k < kend computed)
//   2. softmax in smem (exp values kept unnormalized, 1/l per row)
//   3. write att (normalized, zeros beyond causal limit)
//   4. O = P V   (k-split 16-way per thread, smem reduce), scale by 1/l
// =====================================================================
#define ATTN_SMEM_FLOATS (16*2048 + 256*68 + 16*68 + 16*66 + 16)
#define ATTN_SMEM_BYTES  (ATTN_SMEM_FLOATS*4)

__global__ __launch_bounds__(256) void attn_kernel(float* __restrict__ out_att, int att_mode)
{
    extern __shared__ float sm[];
    float* S    = sm;                       // 16*2048
    float* KV   = S  + 16*2048;             // 256*68
    float* Qs   = KV + 256*68;              // 16*68
    float* QR   = Qs + 16*68;               // 16*66
    float* lrow = QR + 16*66;               // 16

    const int tid = threadIdx.x;
    const int qt  = blockIdx.x;
    const int bh  = blockIdx.y;
    const int q0  = qt * 16;
    const int kend = q0 + 16;
    const size_t qbase = (size_t)bh * TT;

    float* att = att_mode ? g_att : out_att;

    // ---- load Q tile + qrel rows ----
    {
        int t = tid >> 4, d4 = tid & 15;
        *(float4*)&Qs[t*68 + d4*4] =
            *(const float4*)&g_q[(qbase + q0 + t)*DD + d4*4];
    }
    for (int i = tid; i < 16*NR; i += 256) {
        int t = i / NR, r = i % NR;
        QR[t*66 + r] = g_qrel[(qbase + q0 + t)*NR + r];
    }
    __syncthreads();

    // ---- S = Q K^T (+rel, scale) ----
    {
        const int tg = tid >> 6;     // 0..3 (t-group)
        const int kg = tid & 63;     // 0..63 (k lane)
        for (int kc = 0; kc < kend; kc += 256) {
            int klen = min(256, kend - kc);
            if (kc) __syncthreads();
            for (int i = tid; i < klen*16; i += 256) {
                int kk = i >> 4, d4 = i & 15;
                *(float4*)&KV[kk*68 + d4*4] =
                    *(const float4*)&g_k[(qbase + kc + kk)*DD + d4*4];
            }
            __syncthreads();

            float acc[4][4];
            #pragma unroll
            for (int i = 0; i < 4; i++)
                #pragma unroll
                for (int j = 0; j < 4; j++) acc[i][j] = 0.f;

            #pragma unroll
            for (int d4 = 0; d4 < 16; d4++) {
                float4 qv[4], kv[4];
                #pragma unroll
                for (int i = 0; i < 4; i++)
                    qv[i] = *(const float4*)&Qs[(tg*4+i)*68 + d4*4];
                #pragma unroll
                for (int j = 0; j < 4; j++)
                    kv[j] = *(const float4*)&KV[(kg + 64*j)*68 + d4*4];
                #pragma unroll
                for (int i = 0; i < 4; i++)
                    #pragma unroll
                    for (int j = 0; j < 4; j++)
                        acc[i][j] += dot4(qv[i], kv[j]);
            }

            #pragma unroll
            for (int j = 0; j < 4; j++) {
                int kk = kg + 64*j;
                if (kk < klen) {
                    int kglob = kc + kk;
                    #pragma unroll
                    for (int i = 0; i < 4; i++) {
                        int t = tg*4 + i;
                        int qglob = q0 + t;
                        int dd = kglob - qglob;
                        int idx = min(max(dd, -32), 32) + 32;
                        S[t*2048 + kglob] = (acc[i][j] + QR[t*66 + idx]) * 0.125f;
                    }
                }
            }
        }
    }
    __syncthreads();

    // ---- softmax: 8 warps x 2 rows; keep unnormalized exp in S ----
    {
        int warp = tid >> 5, lane = tid & 31;
        #pragma unroll
        for (int tt = 0; tt < 2; tt++) {
            int t = warp*2 + tt;
            float* Srow = S + t*2048;
            int n = q0 + t + 1;                // causal valid length
            float m = -1e30f;
            for (int k = lane; k < n; k += 32) m = fmaxf(m, Srow[k]);
            #pragma unroll
            for (int off = 16; off; off >>= 1)
                m = fmaxf(m, __shfl_xor_sync(0xffffffffu, m, off));
            float l = 0.f;
            for (int k = lane; k < n; k += 32) {
                float e = __expf(Srow[k] - m);
                Srow[k] = e;
                l += e;
            }
            #pragma unroll
            for (int off = 16; off; off >>= 1)
                l += __shfl_xor_sync(0xffffffffu, l, off);
            for (int k = n + lane; k < kend; k += 32) Srow[k] = 0.f; // masked-in-tile
            if (lane == 0) lrow[t] = 1.f / l;
        }
    }
    __syncthreads();

    // ---- write att rows (zeros past causal limit) ----
    for (int t = 0; t < 16; t++) {
        float inv = lrow[t];
        int n = q0 + t + 1;
        float* dst = att + ((size_t)bh*TT + (q0 + t)) * TT;
        float* Srow = S + t*2048;
        for (int k4 = tid; k4 < TT/4; k4 += 256) {
            int k = k4*4;
            float4 o = make_float4(0.f, 0.f, 0.f, 0.f);
            if (k + 0 < n) o.x = Srow[k+0]*inv;
            if (k + 1 < n) o.y = Srow[k+1]*inv;
            if (k + 2 < n) o.z = Srow[k+2]*inv;
            if (k + 3 < n) o.w = Srow[k+3]*inv;
            *(float4*)&dst[k] = o;
        }
    }

    // ---- O = P V (k-split: 16 partitions per output) ----
    {
        const int ks = tid & 15;          // k partition
        const int tg = (tid >> 4) & 3;    // t group (4 rows)
        const int dg = tid >> 6;          // d group (16 cols)
        float4 acc[4][4];
        #pragma unroll
        for (int i = 0; i < 4; i++)
            #pragma unroll
            for (int j = 0; j < 4; j++) acc[i][j] = make_float4(0.f,0.f,0.f,0.f);

        for (int kc = 0; kc < kend; kc += 256) {
            int klen = min(256, kend - kc);
            __syncthreads();
            for (int i = tid; i < klen*16; i += 256) {
                int kk = i >> 4, d4 = i & 15;
                *(float4*)&KV[kk*68 + d4*4] =
                    *(const float4*)&g_v[(qbase + kc + kk)*DD + d4*4];
            }
            __syncthreads();

            for (int k = ks; k < klen; k += 16) {
                float p[4];
                #pragma unroll
                for (int i = 0; i < 4; i++)
                    p[i] = S[(tg*4+i)*2048 + kc + k];
                float4 vv[4];
                #pragma unroll
                for (int j = 0; j < 4; j++)
                    vv[j] = *(const float4*)&KV[k*68 + dg*16 + j*4];
                #pragma unroll
                for (int i = 0; i < 4; i++)
                    #pragma unroll
                    for (int j = 0; j < 4; j++) {
                        acc[i][j].x += p[i]*vv[j].x;
                        acc[i][j].y += p[i]*vv[j].y;
                        acc[i][j].z += p[i]*vv[j].z;
                        acc[i][j].w += p[i]*vv[j].w;
                    }
            }
        }
        __syncthreads();
        // stash partials in KV scratch: [ks][t*64+d]
        #pragma unroll
        for (int i = 0; i < 4; i++)
            #pragma unroll
            for (int j = 0; j < 4; j++) {
                int t = tg*4 + i;
                int d = dg*16 + j*4;
                *(float4*)&KV[ks*1024 + t*64 + d] = acc[i][j];
            }
        __syncthreads();
        // reduce 16 partials -> g_o
        {
            float4 sum = make_float4(0.f,0.f,0.f,0.f);
            #pragma unroll
            for (int s2 = 0; s2 < 16; s2++) {
                float4 v = *(const float4*)&KV[s2*1024 + tid*4];
                sum.x += v.x; sum.y += v.y; sum.z += v.z; sum.w += v.w;
            }
            int t = tid >> 4;
            int d = (tid & 15) * 4;
            float inv = lrow[t];
            int b_ = bh >> 4, h_ = bh & 15;
            float4 o = make_float4(sum.x*inv, sum.y*inv, sum.z*inv, sum.w*inv);
            *(float4*)&g_o[((size_t)b_*TT + q0 + t)*CC + h_*64 + d] = o;
        }
    }
}

// =====================================================================
extern "C" void kernel_launch(void* const* d_in, const int* in_sizes, int n_in,
                              void* d_out, int out_size)
{
    const float* x      = (const float*)d_in[0];
    // d_in[1] = mask (tril by construction) — causality applied analytically
    const float* w_attn = (const float*)d_in[2];
    const float* b_attn = (const float*)d_in[3];
    const float* w_proj = (const float*)d_in[4];
    const float* b_proj = (const float*)d_in[5];
    const float* rel_k  = (const float*)d_in[6];
    float* out = (float*)d_out;

    const size_t YS = (size_t)BT*CC;             // 4,194,304
    const size_t AS = (size_t)BH*TT*TT;          // 134,217,728

    float* y_out = out;
    float* att_base = nullptr;
    int att_mode = 1;                            // 1 -> g_att scratch
    if ((size_t)out_size >= YS + AS) {           // concat (y, att)
        y_out = out; att_base = out + YS; att_mode = 0;
    } else if ((size_t)out_size == AS) {         // att only
        att_base = out; att_mode = 0; y_out = nullptr;
    }                                            // else: y only, att -> scratch

    cudaFuncSetAttribute(attn_kernel,
        cudaFuncAttributeMaxDynamicSharedMemorySize, ATTN_SMEM_BYTES);

    // 1. QKV projection -> g_q/g_k/g_v (head-major)
    sgemm_kernel<0><<<dim3(24, 32), 256>>>(x, w_attn, b_attn, nullptr, 3072);
    // 2. relative-position projections
    qrel_kernel<<<BH*TT/32, 256>>>(rel_k);
    // 3. attention + att output + context -> g_o
    attn_kernel<<<dim3(TT/16, BH), 256, ATTN_SMEM_BYTES>>>(att_base, att_mode);
    // 4. output projection -> y
    sgemm_kernel<1><<<dim3(8, 32), 256>>>(nullptr, w_proj, b_proj, y_out, 1024);
}

// round 5
// speedup vs baseline: 1.2923x; 1.2923x over previous
#include <cuda_runtime.h>
#include <cuda_bf16.h>
#include <math.h>
#include <stdint.h>

#define BB 2
#define TT 2048
#define CC 1024
#define HH 16
#define DD 64
#define NR 65                      // 2*MAXREL+1
#define BH (BB*HH)                 // 32
#define BT (BB*TT)                 // 4096

// ---------------- device scratch (no allocations allowed) ----------------
__device__ float g_q[BH*TT*DD];        // [bh][t][d]
__device__ float g_k[BH*TT*DD];
__device__ float g_v[BH*TT*DD];
__device__ float g_qrel[BH*TT*NR];     // [bh][t][r]
__device__ float g_o[BT*CC];           // pre-proj context [b*T+t][h*64+d]
__device__ float g_y[BT*CC];           // fallback y sink
__device__ float g_att[(size_t)BH*TT*TT]; // fallback att sink

// bf16 split operands for tensor-core GEMMs
__device__ __nv_bfloat16 g_xa_hi[BT*CC],  g_xa_lo[BT*CC];     // x split   [M][K]
__device__ __nv_bfloat16 g_oa_hi[BT*CC],  g_oa_lo[BT*CC];     // o split   [M][K]
__device__ __nv_bfloat16 g_wta_hi[3*CC*CC], g_wta_lo[3*CC*CC];// w_attn^T  [N][K]
__device__ __nv_bfloat16 g_wtp_hi[CC*CC],   g_wtp_lo[CC*CC];  // w_proj^T  [N][K]

// ===================== mma.sync helper (sm_80-level PTX, runs on HMMA) =====
__device__ __forceinline__ void mma_16816(float* c, const uint32_t* a, const uint32_t* b) {
    asm volatile("mma.sync.aligned.m16n8k16.row.col.f32.bf16.bf16.f32 "
        "{%0,%1,%2,%3}, {%4,%5,%6,%7}, {%8,%9}, {%0,%1,%2,%3};"
        : "+f"(c[0]), "+f"(c[1]), "+f"(c[2]), "+f"(c[3])
        : "r"(a[0]), "r"(a[1]), "r"(a[2]), "r"(a[3]), "r"(b[0]), "r"(b[1]));
}

// =====================================================================
// Conversion kernels: fp32 -> (hi, lo) bf16 split
// =====================================================================
template<int SRC>   // 0: x param -> g_xa,  1: g_o -> g_oa
__global__ __launch_bounds__(256) void split_kernel(const float* __restrict__ in)
{
    const float* src = (SRC == 0) ? in : (const float*)g_o;
    __nv_bfloat16* hi = (SRC == 0) ? g_xa_hi : g_oa_hi;
    __nv_bfloat16* lo = (SRC == 0) ? g_xa_lo : g_oa_lo;
    int i = blockIdx.x * 256 + threadIdx.x;          // float4 index
    float4 v = ((const float4*)src)[i];
    float a[4] = {v.x, v.y, v.z, v.w};
    __nv_bfloat16 hb[4], lb[4];
    #pragma unroll
    for (int c = 0; c < 4; c++) {
        hb[c] = __float2bfloat16(a[c]);
        lb[c] = __float2bfloat16(a[c] - __bfloat162float(hb[c]));
    }
    ((__nv_bfloat162*)hi)[i*2+0] = __halves2bfloat162(hb[0], hb[1]);
    ((__nv_bfloat162*)hi)[i*2+1] = __halves2bfloat162(hb[2], hb[3]);
    ((__nv_bfloat162*)lo)[i*2+0] = __halves2bfloat162(lb[0], lb[1]);
    ((__nv_bfloat162*)lo)[i*2+1] = __halves2bfloat162(lb[2], lb[3]);
}

// W[K=1024, N] -> Wt_hi/lo[N][K] bf16 (transpose + split)
template<int WSEL>  // 0: w_attn -> g_wta, 1: w_proj -> g_wtp
__global__ __launch_bounds__(256) void wsplit_kernel(const float* __restrict__ W, int N)
{
    __shared__ float ts[32][33];
    __nv_bfloat16* hi = (WSEL == 0) ? g_wta_hi : g_wtp_hi;
    __nv_bfloat16* lo = (WSEL == 0) ? g_wta_lo : g_wtp_lo;
    int nx = blockIdx.x * 32, kx = blockIdx.y * 32;
    int tx = threadIdx.x, ty = threadIdx.y;
    #pragma unroll
    for (int j = ty; j < 32; j += 8)
        ts[j][tx] = W[(size_t)(kx + j)*N + nx + tx];
    __syncthreads();
    #pragma unroll
    for (int j = ty; j < 32; j += 8) {
        float v = ts[tx][j];
        __nv_bfloat16 h = __float2bfloat16(v);
        __nv_bfloat16 l = __float2bfloat16(v - __bfloat162float(h));
        hi[(size_t)(nx + j)*CC + kx + tx] = h;
        lo[(size_t)(nx + j)*CC + kx + tx] = l;
    }
}

// =====================================================================
// mma.sync bf16x3 GEMM: C[4096, N] = A[4096,1024] @ W (W stored ^T [N][K])
// MODE 0: A = g_xa (x), B = g_wta, scatter -> g_q/g_k/g_v + bias (N=3072)
// MODE 1: A = g_oa (o), B = g_wtp, out -> y + bias (N=1024)
// CTA tile 128x128, 8 warps (2x4), warp tile 64x32, K-chunk 64.
// Fragments loaded with plain LDS.b32 (textbook per-lane mapping).
// smem rows padded to 72 bf16 -> conflict-free fragment loads.
// =====================================================================
#define LDA 72
#define SM_ARR (128*LDA)                 // elems per array
#define GEMM_SMEM_BYTES (4*SM_ARR*2)     // 73728

template<int MODE>
__global__ __launch_bounds__(256) void mma_gemm_kernel(const float* __restrict__ bias,
                                                       float* __restrict__ outp)
{
    extern __shared__ __nv_bfloat16 sb[];
    __nv_bfloat16* sAh = sb;
    __nv_bfloat16* sAl = sb + SM_ARR;
    __nv_bfloat16* sBh = sb + 2*SM_ARR;
    __nv_bfloat16* sBl = sb + 3*SM_ARR;

    const int tid  = threadIdx.x;
    const int wid  = tid >> 5, lane = tid & 31;
    const int wm   = wid >> 2, wn = wid & 3;       // warp grid 2x4
    const int m0   = blockIdx.y * 128;
    const int n0   = blockIdx.x * 128;

    const __nv_bfloat16* Ah = (MODE == 0) ? g_xa_hi : g_oa_hi;
    const __nv_bfloat16* Al = (MODE == 0) ? g_xa_lo : g_oa_lo;
    const __nv_bfloat16* Bh = (MODE == 0) ? g_wta_hi : g_wtp_hi;
    const __nv_bfloat16* Bl = (MODE == 0) ? g_wta_lo : g_wtp_lo;

    float acc[4][4][4];
    #pragma unroll
    for (int i = 0; i < 4; i++)
        #pragma unroll
        for (int j = 0; j < 4; j++)
            #pragma unroll
            for (int c = 0; c < 4; c++) acc[i][j][c] = 0.f;

    // textbook m16n8k16 fragment lane mapping
    const int g  = lane >> 2;          // 0..7
    const int t2 = (lane & 3) * 2;     // 0,2,4,6

    for (int kt = 0; kt < 16; kt++) {
        const int k0 = kt * 64;
        #pragma unroll
        for (int it = 0; it < 4; it++) {
            int i = tid + it * 256;
            int r = i >> 3, c8 = i & 7;
            size_t ga = (size_t)(m0 + r) * CC + k0 + c8 * 8;
            size_t gb = (size_t)(n0 + r) * CC + k0 + c8 * 8;
            int so = r * LDA + c8 * 8;
            *(float4*)&sAh[so] = *(const float4*)&Ah[ga];
            *(float4*)&sAl[so] = *(const float4*)&Al[ga];
            *(float4*)&sBh[so] = *(const float4*)&Bh[gb];
            *(float4*)&sBl[so] = *(const float4*)&Bl[gb];
        }
        __syncthreads();

        #pragma unroll
        for (int ks = 0; ks < 4; ks++) {
            const int kb = ks * 16 + t2;
            uint32_t ah[4][4], al[4][4];
            #pragma unroll
            for (int tm = 0; tm < 4; tm++) {
                int r0 = (wm*64 + tm*16 + g) * LDA + kb;   // rows g / g+8
                int r1 = r0 + 8 * LDA;
                ah[tm][0] = *(const uint32_t*)&sAh[r0];
                ah[tm][1] = *(const uint32_t*)&sAh[r1];
                ah[tm][2] = *(const uint32_t*)&sAh[r0 + 8];
                ah[tm][3] = *(const uint32_t*)&sAh[r1 + 8];
                al[tm][0] = *(const uint32_t*)&sAl[r0];
                al[tm][1] = *(const uint32_t*)&sAl[r1];
                al[tm][2] = *(const uint32_t*)&sAl[r0 + 8];
                al[tm][3] = *(const uint32_t*)&sAl[r1 + 8];
            }
            #pragma unroll
            for (int tn = 0; tn < 4; tn++) {
                int rb = (wn*32 + tn*8 + g) * LDA + kb;
                uint32_t bh[2], bl[2];
                bh[0] = *(const uint32_t*)&sBh[rb];
                bh[1] = *(const uint32_t*)&sBh[rb + 8];
                bl[0] = *(const uint32_t*)&sBl[rb];
                bl[1] = *(const uint32_t*)&sBl[rb + 8];
                #pragma unroll
                for (int tm = 0; tm < 4; tm++) {
                    mma_16816(acc[tm][tn], ah[tm], bh);
                    mma_16816(acc[tm][tn], ah[tm], bl);
                    mma_16816(acc[tm][tn], al[tm], bh);
                }
            }
        }
        __syncthreads();
    }

    // ---- epilogue: regs -> gmem (+bias), scatter for MODE 0 ----
    const int lr = lane >> 2;          // 0..7
    const int lc = (lane & 3) * 2;     // 0,2,4,6
    #pragma unroll
    for (int tm = 0; tm < 4; tm++) {
        #pragma unroll
        for (int tn = 0; tn < 4; tn++) {
            int c = n0 + wn*32 + tn*8 + lc;
            float b0 = bias[c], b1 = bias[c+1];
            #pragma unroll
            for (int half = 0; half < 2; half++) {
                int m = m0 + wm*64 + tm*16 + lr + half*8;
                float v0 = acc[tm][tn][half*2+0] + b0;
                float v1 = acc[tm][tn][half*2+1] + b1;
                if (MODE == 0) {
                    int which = c >> 10, hh = (c >> 6) & 15, dd = c & 63;
                    int b_ = m >> 11, t_ = m & 2047;
                    float* dst = (which == 0) ? g_q : (which == 1) ? g_k : g_v;
                    float2* p = (float2*)&dst[((size_t)(b_*HH + hh)*TT + t_)*DD + dd];
                    *p = make_float2(v0, v1);
                } else {
                    float* dst = outp ? outp : g_y;
                    *(float2*)&dst[(size_t)m*CC + c] = make_float2(v0, v1);
                }
            }
        }
    }
}

// =====================================================================
// qrel[bh*T + t][r] = q[bh][t][:] . rel_k_table[r][:]
// =====================================================================
__device__ __forceinline__ float dot4(float4 a, float4 b) {
    return a.x*b.x + a.y*b.y + a.z*b.z + a.w*b.w;
}

__global__ __launch_bounds__(256) void qrel_kernel(const float* __restrict__ rel)
{
    __shared__ float rs[NR*64];
    __shared__ float qs[32*64];
    const int tid = threadIdx.x;
    const int r0  = blockIdx.x * 32;

    for (int i = tid; i < NR*16; i += 256)
        ((float4*)rs)[i] = ((const float4*)rel)[i];
    for (int i = tid; i < 32*16; i += 256) {
        int t = i >> 4, d4 = i & 15;
        *(float4*)&qs[t*64 + d4*4] = *(const float4*)&g_q[(size_t)(r0+t)*64 + d4*4];
    }
    __syncthreads();

    for (int i = tid; i < 32*NR; i += 256) {
        int t = i / NR, r = i % NR;
        const float4* qq = (const float4*)&qs[t*64];
        const float4* rr = (const float4*)&rs[r*64];
        float acc = 0.f;
        #pragma unroll
        for (int d4 = 0; d4 < 16; d4++) acc += dot4(qq[d4], rr[d4]);
        g_qrel[(size_t)(r0+t)*NR + r] = acc;
    }
}

// =====================================================================
// Attention (fp32, unchanged from R1): block = (qt, bh), 16 q-rows.
// =====================================================================
#define ATTN_SMEM_FLOATS (16*2048 + 256*68 + 16*68 + 16*66 + 16)
#define ATTN_SMEM_BYTES  (ATTN_SMEM_FLOATS*4)

__global__ __launch_bounds__(256) void attn_kernel(float* __restrict__ out_att, int att_mode)
{
    extern __shared__ float sm[];
    float* S    = sm;
    float* KV   = S  + 16*2048;
    float* Qs   = KV + 256*68;
    float* QR   = Qs + 16*68;
    float* lrow = QR + 16*66;

    const int tid = threadIdx.x;
    const int qt  = blockIdx.x;
    const int bh  = blockIdx.y;
    const int q0  = qt * 16;
    const int kend = q0 + 16;
    const size_t qbase = (size_t)bh * TT;

    float* att = att_mode ? g_att : out_att;

    {
        int t = tid >> 4, d4 = tid & 15;
        *(float4*)&Qs[t*68 + d4*4] =
            *(const float4*)&g_q[(qbase + q0 + t)*DD + d4*4];
    }
    for (int i = tid; i < 16*NR; i += 256) {
        int t = i / NR, r = i % NR;
        QR[t*66 + r] = g_qrel[(qbase + q0 + t)*NR + r];
    }
    __syncthreads();

    // ---- S = Q K^T (+rel, scale) ----
    {
        const int tg = tid >> 6;
        const int kg = tid & 63;
        for (int kc = 0; kc < kend; kc += 256) {
            int klen = min(256, kend - kc);
            if (kc) __syncthreads();
            for (int i = tid; i < klen*16; i += 256) {
                int kk = i >> 4, d4 = i & 15;
                *(float4*)&KV[kk*68 + d4*4] =
                    *(const float4*)&g_k[(qbase + kc + kk)*DD + d4*4];
            }
            __syncthreads();

            float acc[4][4];
            #pragma unroll
            for (int i = 0; i < 4; i++)
                #pragma unroll
                for (int j = 0; j < 4; j++) acc[i][j] = 0.f;

            #pragma unroll
            for (int d4 = 0; d4 < 16; d4++) {
                float4 qv[4], kv[4];
                #pragma unroll
                for (int i = 0; i < 4; i++)
                    qv[i] = *(const float4*)&Qs[(tg*4+i)*68 + d4*4];
                #pragma unroll
                for (int j = 0; j < 4; j++)
                    kv[j] = *(const float4*)&KV[(kg + 64*j)*68 + d4*4];
                #pragma unroll
                for (int i = 0; i < 4; i++)
                    #pragma unroll
                    for (int j = 0; j < 4; j++)
                        acc[i][j] += dot4(qv[i], kv[j]);
            }

            #pragma unroll
            for (int j = 0; j < 4; j++) {
                int kk = kg + 64*j;
                if (kk < klen) {
                    int kglob = kc + kk;
                    #pragma unroll
                    for (int i = 0; i < 4; i++) {
                        int t = tg*4 + i;
                        int qglob = q0 + t;
                        int dd = kglob - qglob;
                        int idx = min(max(dd, -32), 32) + 32;
                        S[t*2048 + kglob] = (acc[i][j] + QR[t*66 + idx]) * 0.125f;
                    }
                }
            }
        }
    }
    __syncthreads();

    // ---- softmax ----
    {
        int warp = tid >> 5, lane = tid & 31;
        #pragma unroll
        for (int tt = 0; tt < 2; tt++) {
            int t = warp*2 + tt;
            float* Srow = S + t*2048;
            int n = q0 + t + 1;
            float m = -1e30f;
            for (int k = lane; k < n; k += 32) m = fmaxf(m, Srow[k]);
            #pragma unroll
            for (int off = 16; off; off >>= 1)
                m = fmaxf(m, __shfl_xor_sync(0xffffffffu, m, off));
            float l = 0.f;
            for (int k = lane; k < n; k += 32) {
                float e = __expf(Srow[k] - m);
                Srow[k] = e;
                l += e;
            }
            #pragma unroll
            for (int off = 16; off; off >>= 1)
                l += __shfl_xor_sync(0xffffffffu, l, off);
            for (int k = n + lane; k < kend; k += 32) Srow[k] = 0.f;
            if (lane == 0) lrow[t] = 1.f / l;
        }
    }
    __syncthreads();

    // ---- write att rows ----
    for (int t = 0; t < 16; t++) {
        float inv = lrow[t];
        int n = q0 + t + 1;
        float* dst = att + ((size_t)bh*TT + (q0 + t)) * TT;
        float* Srow = S + t*2048;
        for (int k4 = tid; k4 < TT/4; k4 += 256) {
            int k = k4*4;
            float4 o = make_float4(0.f, 0.f, 0.f, 0.f);
            if (k + 0 < n) o.x = Srow[k+0]*inv;
            if (k + 1 < n) o.y = Srow[k+1]*inv;
            if (k + 2 < n) o.z = Srow[k+2]*inv;
            if (k + 3 < n) o.w = Srow[k+3]*inv;
            *(float4*)&dst[k] = o;
        }
    }

    // ---- O = P V ----
    {
        const int ks = tid & 15;
        const int tg = (tid >> 4) & 3;
        const int dg = tid >> 6;
        float4 acc[4][4];
        #pragma unroll
        for (int i = 0; i < 4; i++)
            #pragma unroll
            for (int j = 0; j < 4; j++) acc[i][j] = make_float4(0.f,0.f,0.f,0.f);

        for (int kc = 0; kc < kend; kc += 256) {
            int klen = min(256, kend - kc);
            __syncthreads();
            for (int i = tid; i < klen*16; i += 256) {
                int kk = i >> 4, d4 = i & 15;
                *(float4*)&KV[kk*68 + d4*4] =
                    *(const float4*)&g_v[(qbase + kc + kk)*DD + d4*4];
            }
            __syncthreads();

            for (int k = ks; k < klen; k += 16) {
                float p[4];
                #pragma unroll
                for (int i = 0; i < 4; i++)
                    p[i] = S[(tg*4+i)*2048 + kc + k];
                float4 vv[4];
                #pragma unroll
                for (int j = 0; j < 4; j++)
                    vv[j] = *(const float4*)&KV[k*68 + dg*16 + j*4];
                #pragma unroll
                for (int i = 0; i < 4; i++)
                    #pragma unroll
                    for (int j = 0; j < 4; j++) {
                        acc[i][j].x += p[i]*vv[j].x;
                        acc[i][j].y += p[i]*vv[j].y;
                        acc[i][j].z += p[i]*vv[j].z;
                        acc[i][j].w += p[i]*vv[j].w;
                    }
            }
        }
        __syncthreads();
        #pragma unroll
        for (int i = 0; i < 4; i++)
            #pragma unroll
            for (int j = 0; j < 4; j++) {
                int t = tg*4 + i;
                int d = dg*16 + j*4;
                *(float4*)&KV[ks*1024 + t*64 + d] = acc[i][j];
            }
        __syncthreads();
        {
            float4 sum = make_float4(0.f,0.f,0.f,0.f);
            #pragma unroll
            for (int s2 = 0; s2 < 16; s2++) {
                float4 v = *(const float4*)&KV[s2*1024 + tid*4];
                sum.x += v.x; sum.y += v.y; sum.z += v.z; sum.w += v.w;
            }
            int t = tid >> 4;
            int d = (tid & 15) * 4;
            float inv = lrow[t];
            int b_ = bh >> 4, h_ = bh & 15;
            float4 o = make_float4(sum.x*inv, sum.y*inv, sum.z*inv, sum.w*inv);
            *(float4*)&g_o[((size_t)b_*TT + q0 + t)*CC + h_*64 + d] = o;
        }
    }
}

// =====================================================================
extern "C" void kernel_launch(void* const* d_in, const int* in_sizes, int n_in,
                              void* d_out, int out_size)
{
    const float* x      = (const float*)d_in[0];
    const float* w_attn = (const float*)d_in[2];
    const float* b_attn = (const float*)d_in[3];
    const float* w_proj = (const float*)d_in[4];
    const float* b_proj = (const float*)d_in[5];
    const float* rel_k  = (const float*)d_in[6];
    float* out = (float*)d_out;

    const size_t YS = (size_t)BT*CC;
    const size_t AS = (size_t)BH*TT*TT;

    float* y_out = out;
    float* att_base = nullptr;
    int att_mode = 1;
    if ((size_t)out_size >= YS + AS) {
        y_out = out; att_base = out + YS; att_mode = 0;
    } else if ((size_t)out_size == AS) {
        att_base = out; att_mode = 0; y_out = nullptr;
    }

    cudaFuncSetAttribute(attn_kernel,
        cudaFuncAttributeMaxDynamicSharedMemorySize, ATTN_SMEM_BYTES);
    cudaFuncSetAttribute(mma_gemm_kernel<0>,
        cudaFuncAttributeMaxDynamicSharedMemorySize, GEMM_SMEM_BYTES);
    cudaFuncSetAttribute(mma_gemm_kernel<1>,
        cudaFuncAttributeMaxDynamicSharedMemorySize, GEMM_SMEM_BYTES);

    // 1. operand conversion (split + weight transpose-split)
    split_kernel<0><<<BT*CC/4/256, 256>>>(x);
    wsplit_kernel<0><<<dim3(3*CC/32, CC/32), dim3(32,8)>>>(w_attn, 3*CC);
    wsplit_kernel<1><<<dim3(CC/32,   CC/32), dim3(32,8)>>>(w_proj, CC);
    // 2. QKV projection (mma.sync bf16x3) -> g_q/g_k/g_v (head-major, +bias)
    mma_gemm_kernel<0><<<dim3(24, 32), 256, GEMM_SMEM_BYTES>>>(b_attn, nullptr);
    // 3. relative-position projections
    qrel_kernel<<<BH*TT/32, 256>>>(rel_k);
    // 4. attention + att output + context -> g_o
    attn_kernel<<<dim3(TT/16, BH), 256, ATTN_SMEM_BYTES>>>(att_base, att_mode);
    // 5. split o, output projection (mma.sync bf16x3) -> y
    split_kernel<1><<<BT*CC/4/256, 256>>>(nullptr);
    // FIX R5: grid.x was 4 (leftover from 256-wide R2 tiles) -> only half of
    // y's columns were written. 128-wide tiles need 8 blocks for N=1024.
    mma_gemm_kernel<1><<<dim3(8, 32), 256, GEMM_SMEM_BYTES>>>(b_proj, y_out);
}